// round 5
// baseline (speedup 1.0000x reference)
#include <cuda_runtime.h>
#include <stdint.h>
#include <math.h>

#define BATCH 64
#define SEQ   256
#define DIM   1024
#define BETA_C 0.75f
#define TEMP_C 0.1f

// ---- hybrid warp-specialized GEMM tiling ----
#define BM 256            // rows/CTA: 128 HMMA (warps 0-7) + 128 FFMA2 (warps 8-15)
#define BN 128
#define BK 16
#define NKT (DIM / BK)    // 64 chunks
// stage layout (floats)
#define OFF_FA 0                          // HMMA A frags: 2048
#define OFF_FB 2048                       // HMMA B frags: 2048
#define OFF_AT 4096                       // A bottom, K-major [16][132]
#define OFF_BD (4096 + 16 * 132)          // B duplicated pairs [16][264]
#define STAGE_FLOATS (4096 + 16 * 132 + 16 * 264)   // 10432
#define SMEM_TOTAL (2 * STAGE_FLOATS * 4)           // 83456 B

// ---------------- device scratch ----------------
__device__ float g_i[BATCH * DIM];
__device__ float g_iCi[BATCH * DIM];
__device__ float g_co[BATCH * DIM];
__device__ float g_E[BATCH];
__device__ float g_simn[BATCH * SEQ];
__device__ float g_sig[BATCH * SEQ];
__device__ float g_Wt[DIM * DIM];

// ---------------- K0: transpose weight ----------------
__global__ void k_transpose(const float* __restrict__ W) {
    __shared__ float t[32][33];
    int x = blockIdx.x * 32 + threadIdx.x;
    int y0 = blockIdx.y * 32;
#pragma unroll
    for (int j = 0; j < 32; j += 8)
        t[threadIdx.y + j][threadIdx.x] = W[(size_t)(y0 + threadIdx.y + j) * DIM + x];
    __syncthreads();
    int x2 = blockIdx.y * 32 + threadIdx.x;
    int y2 = blockIdx.x * 32;
#pragma unroll
    for (int j = 0; j < 32; j += 8)
        g_Wt[(size_t)(y2 + threadIdx.y + j) * DIM + x2] = t[threadIdx.x][threadIdx.y + j];
}

// ---------------- K1: gather i ----------------
__global__ void k_gather(const int* __restrict__ prompt_ids,
                         const int* __restrict__ concept_indices,
                         const uint8_t* __restrict__ initted,
                         const float* __restrict__ ema_table,
                         const float* __restrict__ text_enc) {
    int b = blockIdx.x;
    int pid = prompt_ids[b];
    int ci = concept_indices[b];
    bool init = initted[pid] != 0;
    const float* src = init ? (ema_table + (size_t)pid * DIM)
                            : (text_enc + ((size_t)b * SEQ + ci) * DIM);
    for (int d = threadIdx.x; d < DIM; d += blockDim.x)
        g_i[b * DIM + d] = src[d];
}

// ---------------- K2: small GEMMs ----------------
__global__ void k_smallgemm(const float* __restrict__ Cinv) {
    const float* __restrict__ M = (blockIdx.z == 0) ? Cinv : g_Wt;
    float* __restrict__ out = (blockIdx.z == 0) ? g_iCi : g_co;
    int d = blockIdx.x * 128 + threadIdx.x;
    int b0 = blockIdx.y * 8;
    __shared__ float ish[8][128];
    float acc[8];
#pragma unroll
    for (int r = 0; r < 8; r++) acc[r] = 0.0f;
    for (int k0 = 0; k0 < DIM; k0 += 128) {
#pragma unroll
        for (int r = 0; r < 8; r++)
            ish[r][threadIdx.x] = g_i[(b0 + r) * DIM + k0 + threadIdx.x];
        __syncthreads();
#pragma unroll 4
        for (int kk = 0; kk < 128; kk++) {
            float m = M[(size_t)(k0 + kk) * DIM + d];
#pragma unroll
            for (int r = 0; r < 8; r++) acc[r] += ish[r][kk] * m;
        }
        __syncthreads();
    }
#pragma unroll
    for (int r = 0; r < 8; r++) out[(b0 + r) * DIM + d] = acc[r];
}

// ---------------- K3: i_energy ----------------
__global__ void k_energy() {
    int b = blockIdx.x, tid = threadIdx.x;
    float s = 0.0f;
    for (int d = tid; d < DIM; d += 256)
        s += g_iCi[b * DIM + d] * g_i[b * DIM + d];
#pragma unroll
    for (int o = 16; o; o >>= 1) s += __shfl_xor_sync(0xffffffffu, s, o);
    __shared__ float red[8];
    if ((tid & 31) == 0) red[tid >> 5] = s;
    __syncthreads();
    if (tid < 8) {
        float t = red[tid];
#pragma unroll
        for (int o = 4; o; o >>= 1) t += __shfl_xor_sync(0xffu, t, o);
        if (tid == 0) g_E[b] = t;
    }
}

// ---------------- K4: sim + sigmoid ----------------
__global__ void k_sim(const float* __restrict__ text_enc) {
    int warp = threadIdx.x >> 5, lane = threadIdx.x & 31;
    int m = blockIdx.x * 8 + warp;
    int b = m >> 8;
    const float4* x = (const float4*)(text_enc + (size_t)m * DIM);
    const float4* c = (const float4*)(g_iCi + (size_t)b * DIM);
    float s = 0.0f;
#pragma unroll
    for (int it = 0; it < 8; it++) {
        int idx = it * 32 + lane;
        float4 xv = x[idx], cv = c[idx];
        s += xv.x * cv.x + xv.y * cv.y + xv.z * cv.z + xv.w * cv.w;
    }
#pragma unroll
    for (int o = 16; o; o >>= 1) s += __shfl_xor_sync(0xffffffffu, s, o);
    if (lane == 0) {
        float simn = s / g_E[b];
        g_simn[m] = simn;
        g_sig[m] = 1.0f / (1.0f + expf(-(simn - BETA_C) / TEMP_C));
    }
}

// ---------------- helpers ----------------
__device__ __forceinline__ uint32_t f2tf32(float x) {
    uint32_t r;
    asm("cvt.rna.tf32.f32 %0, %1;" : "=r"(r) : "f"(x));
    return r;
}
__device__ __forceinline__ void mma_tf32(float* c, const uint4& a, const uint2& b) {
    asm volatile(
        "mma.sync.aligned.m16n8k8.row.col.f32.tf32.tf32.f32 "
        "{%0,%1,%2,%3}, {%4,%5,%6,%7}, {%8,%9}, {%0,%1,%2,%3};"
        : "+f"(c[0]), "+f"(c[1]), "+f"(c[2]), "+f"(c[3])
        : "r"(a.x), "r"(a.y), "r"(a.z), "r"(a.w), "r"(b.x), "r"(b.y));
}
__device__ __forceinline__ void fma2(unsigned long long& c, unsigned long long a,
                                     unsigned long long b) {
    asm("fma.rn.f32x2 %0, %1, %2, %0;" : "+l"(c) : "l"(a), "l"(b));
}
__device__ __forceinline__ float2 unpack2(unsigned long long p) {
    float lo, hi;
    asm("mov.b64 {%0, %1}, %2;" : "=f"(lo), "=f"(hi) : "l"(p));
    return make_float2(lo, hi);
}

// HMMA fragment stores (validated R3/R4); ks in {0,1} for BK=16
__device__ __forceinline__ void sts_fragA(float* base, int mrow, int k0, const float4 v) {
    int ks = k0 >> 3, krh = (k0 >> 2) & 1;
    int mt = mrow >> 4, mr = mrow & 15;
    float* p = base + OFF_FA + (((ks * 8 + mt) * 32 + ((mr & 7) << 2)) << 2) + ((mr >> 3) | (krh << 1));
    p[0] = v.x; p[4] = v.y; p[8] = v.z; p[12] = v.w;
}
__device__ __forceinline__ void sts_fragB(float* base, int nrow, int k0, const float4 v) {
    int ks = k0 >> 3, krh = (k0 >> 2) & 1;
    int nt = nrow >> 3, nr = nrow & 7;
    float* p = base + OFF_FB + (((ks * 16 + nt) * 32 + (nr << 2)) << 1) + krh;
    p[0] = v.x; p[2] = v.y; p[4] = v.z; p[6] = v.w;
}

// producer store of one chunk slice
__device__ __forceinline__ void store_stage(float* st, int prow, int pseg,
                                            const float4& va0, const float4& va1,
                                            const float4& vb) {
    float4 ta = make_float4(__uint_as_float(f2tf32(va0.x)), __uint_as_float(f2tf32(va0.y)),
                            __uint_as_float(f2tf32(va0.z)), __uint_as_float(f2tf32(va0.w)));
    sts_fragA(st, prow, pseg, ta);
    float4 tb = make_float4(__uint_as_float(f2tf32(vb.x)), __uint_as_float(f2tf32(vb.y)),
                            __uint_as_float(f2tf32(vb.z)), __uint_as_float(f2tf32(vb.w)));
    sts_fragB(st, prow, pseg, tb);
    // A bottom K-major
    st[OFF_AT + (pseg + 0) * 132 + prow] = va1.x;
    st[OFF_AT + (pseg + 1) * 132 + prow] = va1.y;
    st[OFF_AT + (pseg + 2) * 132 + prow] = va1.z;
    st[OFF_AT + (pseg + 3) * 132 + prow] = va1.w;
    // B duplicated pairs
    *(float2*)(st + OFF_BD + (pseg + 0) * 264 + 2 * prow) = make_float2(vb.x, vb.x);
    *(float2*)(st + OFF_BD + (pseg + 1) * 264 + 2 * prow) = make_float2(vb.y, vb.y);
    *(float2*)(st + OFF_BD + (pseg + 2) * 264 + 2 * prow) = make_float2(vb.z, vb.z);
    *(float2*)(st + OFF_BD + (pseg + 3) * 264 + 2 * prow) = make_float2(vb.w, vb.w);
}

// ---------------- K5: warp-specialized hybrid GEMM + fused epilogue ----------------
__global__ __launch_bounds__(512, 1) void k_main(
    const float* __restrict__ A,              // text_enc [16384][1024]
    const float* __restrict__ W,              // weight   [1024][1024]
    const int* __restrict__ prompt_ids,
    const uint8_t* __restrict__ initted,
    const float* __restrict__ outputs_table,  // [512][256][1024]
    float* __restrict__ out) {
    extern __shared__ float sf[];

    const int tid = threadIdx.x;
    const int wid = tid >> 5, lane = tid & 31;
    const int m0 = blockIdx.y * BM;
    const int n0 = blockIdx.x * BN;
    const int b = blockIdx.y;                 // BM == SEQ
    const int pid = prompt_ids[b];
    const bool init = initted[pid] != 0;

    // producer mapping (all 512 threads)
    const int prow = tid >> 2;                // 0..127
    const int pseg = (tid & 3) * 4;           // 0,4,8,12
    const float* pA0 = A + (size_t)(m0 + prow) * DIM + pseg;
    const float* pA1 = A + (size_t)(m0 + 128 + prow) * DIM + pseg;
    const float* pB  = W + (size_t)(n0 + prow) * DIM + pseg;

    float4 va0 = *(const float4*)pA0;
    float4 va1 = *(const float4*)pA1;
    float4 vb  = *(const float4*)pB;
    store_stage(sf, prow, pseg, va0, va1, vb);
    __syncthreads();

    if (wid < 8) {
        // ================= HMMA path: rows m0..m0+127 =================
        const int wm = wid & 1, wn = wid >> 1;
        float hacc[4][4][4];
#pragma unroll
        for (int i = 0; i < 4; i++)
#pragma unroll
            for (int j = 0; j < 4; j++)
#pragma unroll
                for (int r = 0; r < 4; r++) hacc[i][j][r] = 0.0f;

        for (int kt = 0; kt < NKT; kt++) {
            float* cur = sf + (kt & 1) * STAGE_FLOATS;
            if (kt + 1 < NKT) {
                int ko = (kt + 1) * BK;
                va0 = *(const float4*)(pA0 + ko);
                va1 = *(const float4*)(pA1 + ko);
                vb  = *(const float4*)(pB + ko);
            }
#pragma unroll
            for (int ks = 0; ks < 2; ks++) {
                uint4 afr[4];
                uint2 bfr[4];
#pragma unroll
                for (int i = 0; i < 4; i++)
                    afr[i] = *(const uint4*)(cur + OFF_FA + (((ks * 8 + wm * 4 + i) * 32 + lane) << 2));
#pragma unroll
                for (int j = 0; j < 4; j++)
                    bfr[j] = *(const uint2*)(cur + OFF_FB + (((ks * 16 + wn * 4 + j) * 32 + lane) << 1));
#pragma unroll
                for (int i = 0; i < 4; i++)
#pragma unroll
                    for (int j = 0; j < 4; j++)
                        mma_tf32(hacc[i][j], afr[i], bfr[j]);
            }
            if (kt + 1 < NKT) {
                __syncthreads();
                store_stage(sf + ((kt + 1) & 1) * STAGE_FLOATS, prow, pseg, va0, va1, vb);
                __syncthreads();
            }
        }

        // epilogue (HMMA half)
        float2 co2[4];
#pragma unroll
        for (int j = 0; j < 4; j++)
            co2[j] = *(const float2*)&g_co[b * DIM + n0 + wn * 32 + j * 8 + (lane & 3) * 2];
#pragma unroll
        for (int i = 0; i < 4; i++) {
            int gr0 = m0 + wm * 64 + i * 16 + (lane >> 2);
            int gr1 = gr0 + 8;
            float simn0 = g_simn[gr0], sig0 = g_sig[gr0];
            float simn1 = g_simn[gr1], sig1 = g_sig[gr1];
            const float* ot0 = outputs_table + ((size_t)pid * SEQ + (gr0 & (SEQ - 1))) * DIM;
            const float* ot1 = outputs_table + ((size_t)pid * SEQ + (gr1 & (SEQ - 1))) * DIM;
#pragma unroll
            for (int j = 0; j < 4; j++) {
                int col = n0 + wn * 32 + j * 8 + (lane & 3) * 2;
                float c0 = hacc[i][j][0], c1 = hacc[i][j][1];
                float c2 = hacc[i][j][2], c3 = hacc[i][j][3];
                float o0 = init ? ot0[col] : c0;
                float o1 = init ? ot0[col + 1] : c1;
                float o2 = init ? ot1[col] : c2;
                float o3 = init ? ot1[col + 1] : c3;
                float2 v0 = make_float2(c0 - simn0 * co2[j].x + sig0 * o0,
                                        c1 - simn0 * co2[j].y + sig0 * o1);
                float2 v1 = make_float2(c2 - simn1 * co2[j].x + sig1 * o2,
                                        c3 - simn1 * co2[j].y + sig1 * o3);
                *(float2*)&out[(size_t)gr0 * DIM + col] = v0;
                *(float2*)&out[(size_t)gr1 * DIM + col] = v1;
            }
        }
    } else {
        // ================= FFMA2 path: rows m0+128..m0+255 =================
        const int fw = wid - 8;
        const int wrow = fw >> 1;                  // 0..3
        const int wcol = fw & 1;                   // 0..1
        const int rbase = wrow * 32 + (lane >> 3) * 8;   // local row in bottom half
        const int cbase = wcol * 64 + (lane & 7) * 8;    // local col

        unsigned long long facc[4][8];
#pragma unroll
        for (int rp = 0; rp < 4; rp++)
#pragma unroll
            for (int c = 0; c < 8; c++) facc[rp][c] = 0ULL;

        for (int kt = 0; kt < NKT; kt++) {
            float* cur = sf + (kt & 1) * STAGE_FLOATS;
            if (kt + 1 < NKT) {
                int ko = (kt + 1) * BK;
                va0 = *(const float4*)(pA0 + ko);
                va1 = *(const float4*)(pA1 + ko);
                vb  = *(const float4*)(pB + ko);
            }
#pragma unroll 8
            for (int k = 0; k < BK; k++) {
                const float* at = cur + OFF_AT + k * 132 + rbase;
                const float* bd = cur + OFF_BD + k * 264 + 2 * cbase;
                unsigned long long a2[4], b2[8];
#pragma unroll
                for (int rp = 0; rp < 4; rp++)
                    a2[rp] = *(const unsigned long long*)(at + 2 * rp);
#pragma unroll
                for (int c = 0; c < 8; c++)
                    b2[c] = *(const unsigned long long*)(bd + 2 * c);
#pragma unroll
                for (int rp = 0; rp < 4; rp++)
#pragma unroll
                    for (int c = 0; c < 8; c++)
                        fma2(facc[rp][c], a2[rp], b2[c]);
            }
            if (kt + 1 < NKT) {
                __syncthreads();
                store_stage(sf + ((kt + 1) & 1) * STAGE_FLOATS, prow, pseg, va0, va1, vb);
                __syncthreads();
            }
        }

        // epilogue (FFMA half)
        int c0g = n0 + cbase;
        float4 cof0 = *(const float4*)&g_co[b * DIM + c0g];
        float4 cof1 = *(const float4*)&g_co[b * DIM + c0g + 4];
        const float* cop0 = (const float*)&cof0;
        const float* cop1 = (const float*)&cof1;
#pragma unroll
        for (int rp = 0; rp < 4; rp++) {
            int r0 = m0 + 128 + rbase + 2 * rp;
            int r1 = r0 + 1;
            float f0[8], f1[8];
#pragma unroll
            for (int c = 0; c < 8; c++) {
                float2 t = unpack2(facc[rp][c]);
                f0[c] = t.x; f1[c] = t.y;
            }
            float simn0 = g_simn[r0], sig0 = g_sig[r0];
            float simn1 = g_simn[r1], sig1 = g_sig[r1];
            const float* ot0 = outputs_table + ((size_t)pid * SEQ + (r0 & (SEQ - 1))) * DIM;
            const float* ot1 = outputs_table + ((size_t)pid * SEQ + (r1 & (SEQ - 1))) * DIM;
            float4 u0, u1, w0, w1;
            float* up0 = (float*)&u0;
            float* up1 = (float*)&u1;
            float* wp0 = (float*)&w0;
            float* wp1 = (float*)&w1;
#pragma unroll
            for (int c = 0; c < 4; c++) {
                float oa = init ? ot0[c0g + c] : f0[c];
                float ob = init ? ot0[c0g + 4 + c] : f0[4 + c];
                up0[c] = f0[c] - simn0 * cop0[c] + sig0 * oa;
                up1[c] = f0[4 + c] - simn0 * cop1[c] + sig0 * ob;
                float oc = init ? ot1[c0g + c] : f1[c];
                float od = init ? ot1[c0g + 4 + c] : f1[4 + c];
                wp0[c] = f1[c] - simn1 * cop0[c] + sig1 * oc;
                wp1[c] = f1[4 + c] - simn1 * cop1[c] + sig1 * od;
            }
            *(float4*)&out[(size_t)r0 * DIM + c0g] = u0;
            *(float4*)&out[(size_t)r0 * DIM + c0g + 4] = u1;
            *(float4*)&out[(size_t)r1 * DIM + c0g] = w0;
            *(float4*)&out[(size_t)r1 * DIM + c0g + 4] = w1;
        }
    }
}

// --------------------------------- launch ---------------------------------------
extern "C" void kernel_launch(void* const* d_in, const int* in_sizes, int n_in,
                              void* d_out, int out_size) {
    const int*     prompt_ids      = (const int*)d_in[0];
    const float*   text_enc        = (const float*)d_in[1];
    const int*     concept_indices = (const int*)d_in[2];
    const float*   weight          = (const float*)d_in[3];
    const float*   C_inv           = (const float*)d_in[4];
    const uint8_t* initted         = (const uint8_t*)d_in[5];
    const float*   ema_table       = (const float*)d_in[6];
    const float*   outputs_table   = (const float*)d_in[7];
    float*         out             = (float*)d_out;

    (void)in_sizes; (void)n_in; (void)out_size;

    cudaFuncSetAttribute(k_main, cudaFuncAttributeMaxDynamicSharedMemorySize, SMEM_TOTAL);

    k_transpose<<<dim3(DIM / 32, DIM / 32), dim3(32, 8)>>>(weight);
    k_gather<<<BATCH, 256>>>(prompt_ids, concept_indices, initted, ema_table, text_enc);
    k_smallgemm<<<dim3(DIM / 128, BATCH / 8, 2), 128>>>(C_inv);
    k_energy<<<BATCH, 256>>>();
    k_sim<<<(BATCH * SEQ) / 8, 256>>>(text_enc);
    k_main<<<dim3(DIM / BN, (BATCH * SEQ) / BM), 512, SMEM_TOTAL>>>(
        text_enc, weight, prompt_ids, initted, outputs_table, out);
}

// round 6
// speedup vs baseline: 3.5416x; 3.5416x over previous
#include <cuda_runtime.h>
#include <cuda_fp16.h>
#include <stdint.h>
#include <math.h>

#define BATCH 64
#define SEQ   256
#define DIM   1024
#define BETA_C 0.75f
#define TEMP_C 0.1f

// ---- GEMM tiling (fp16 HMMA k16) ----
#define BM 128
#define BN 128
#define BK 32
#define NKT (DIM / BK)              // 32 k-chunks
#define OFF_FB 2048                 // u32 offset of B frags
#define STAGE_U32 4096              // A frags 2048 u32 + B frags 2048 u32 (16 KB)
#define SMEM_TOTAL (2 * STAGE_U32 * 4)   // 32 KB

// ---------------- device scratch ----------------
__device__ float g_i[BATCH * DIM];
__device__ float g_iCi[BATCH * DIM];
__device__ float g_co[BATCH * DIM];
__device__ float g_E[BATCH];
__device__ float g_simn[BATCH * SEQ];
__device__ float g_sig[BATCH * SEQ];
__device__ float g_Wt[DIM * DIM];

// ---------------- K0: transpose weight ----------------
__global__ void k_transpose(const float* __restrict__ W) {
    __shared__ float t[32][33];
    int x = blockIdx.x * 32 + threadIdx.x;
    int y0 = blockIdx.y * 32;
#pragma unroll
    for (int j = 0; j < 32; j += 8)
        t[threadIdx.y + j][threadIdx.x] = W[(size_t)(y0 + threadIdx.y + j) * DIM + x];
    __syncthreads();
    int x2 = blockIdx.y * 32 + threadIdx.x;
    int y2 = blockIdx.x * 32;
#pragma unroll
    for (int j = 0; j < 32; j += 8)
        g_Wt[(size_t)(y2 + threadIdx.y + j) * DIM + x2] = t[threadIdx.x][threadIdx.y + j];
}

// ---------------- K1: gather i ----------------
__global__ void k_gather(const int* __restrict__ prompt_ids,
                         const int* __restrict__ concept_indices,
                         const uint8_t* __restrict__ initted,
                         const float* __restrict__ ema_table,
                         const float* __restrict__ text_enc) {
    int b = blockIdx.x;
    int pid = prompt_ids[b];
    int ci = concept_indices[b];
    bool init = initted[pid] != 0;
    const float* src = init ? (ema_table + (size_t)pid * DIM)
                            : (text_enc + ((size_t)b * SEQ + ci) * DIM);
    for (int d = threadIdx.x; d < DIM; d += blockDim.x)
        g_i[b * DIM + d] = src[d];
}

// ---------------- K2: small GEMMs ----------------
__global__ void k_smallgemm(const float* __restrict__ Cinv) {
    const float* __restrict__ M = (blockIdx.z == 0) ? Cinv : g_Wt;
    float* __restrict__ out = (blockIdx.z == 0) ? g_iCi : g_co;
    int d = blockIdx.x * 128 + threadIdx.x;
    int b0 = blockIdx.y * 8;
    __shared__ float ish[8][128];
    float acc[8];
#pragma unroll
    for (int r = 0; r < 8; r++) acc[r] = 0.0f;
    for (int k0 = 0; k0 < DIM; k0 += 128) {
#pragma unroll
        for (int r = 0; r < 8; r++)
            ish[r][threadIdx.x] = g_i[(b0 + r) * DIM + k0 + threadIdx.x];
        __syncthreads();
#pragma unroll 4
        for (int kk = 0; kk < 128; kk++) {
            float m = M[(size_t)(k0 + kk) * DIM + d];
#pragma unroll
            for (int r = 0; r < 8; r++) acc[r] += ish[r][kk] * m;
        }
        __syncthreads();
    }
#pragma unroll
    for (int r = 0; r < 8; r++) out[(b0 + r) * DIM + d] = acc[r];
}

// ---------------- K3: i_energy ----------------
__global__ void k_energy() {
    int b = blockIdx.x, tid = threadIdx.x;
    float s = 0.0f;
    for (int d = tid; d < DIM; d += 256)
        s += g_iCi[b * DIM + d] * g_i[b * DIM + d];
#pragma unroll
    for (int o = 16; o; o >>= 1) s += __shfl_xor_sync(0xffffffffu, s, o);
    __shared__ float red[8];
    if ((tid & 31) == 0) red[tid >> 5] = s;
    __syncthreads();
    if (tid < 8) {
        float t = red[tid];
#pragma unroll
        for (int o = 4; o; o >>= 1) t += __shfl_xor_sync(0xffu, t, o);
        if (tid == 0) g_E[b] = t;
    }
}

// ---------------- K4: sim + sigmoid ----------------
__global__ void k_sim(const float* __restrict__ text_enc) {
    int warp = threadIdx.x >> 5, lane = threadIdx.x & 31;
    int m = blockIdx.x * 8 + warp;
    int b = m >> 8;
    const float4* x = (const float4*)(text_enc + (size_t)m * DIM);
    const float4* c = (const float4*)(g_iCi + (size_t)b * DIM);
    float s = 0.0f;
#pragma unroll
    for (int it = 0; it < 8; it++) {
        int idx = it * 32 + lane;
        float4 xv = x[idx], cv = c[idx];
        s += xv.x * cv.x + xv.y * cv.y + xv.z * cv.z + xv.w * cv.w;
    }
#pragma unroll
    for (int o = 16; o; o >>= 1) s += __shfl_xor_sync(0xffffffffu, s, o);
    if (lane == 0) {
        float simn = s / g_E[b];
        g_simn[m] = simn;
        g_sig[m] = 1.0f / (1.0f + expf(-(simn - BETA_C) / TEMP_C));
    }
}

// ---------------- helpers ----------------
__device__ __forceinline__ uint32_t h2u(__half2 h) { return *(uint32_t*)&h; }

__device__ __forceinline__ void mma_f16(float* c, const uint4& a, const uint2& b) {
    asm volatile(
        "mma.sync.aligned.m16n8k16.row.col.f32.f16.f16.f32 "
        "{%0,%1,%2,%3}, {%4,%5,%6,%7}, {%8,%9}, {%0,%1,%2,%3};"
        : "+f"(c[0]), "+f"(c[1]), "+f"(c[2]), "+f"(c[3])
        : "r"(a.x), "r"(a.y), "r"(a.z), "r"(a.w), "r"(b.x), "r"(b.y));
}

// fp16 fragment stores for m16n8k16 (row-major A, col-major B)
// A elem (m,k): lane=((m&7)<<2)|((k&15)>>1 & 3), reg=((m>>3)&1)|((k&8)>>2)
__device__ __forceinline__ void sts_fragA(uint32_t* st, int mrow, int k0,
                                          uint32_t h01, uint32_t h23) {
    int ks = k0 >> 4, kin = k0 & 15;
    int lane = ((mrow & 7) << 2) | ((kin >> 1) & 3);
    int reg = ((mrow >> 3) & 1) | ((kin >> 3) << 1);
    int mt = mrow >> 4;
    uint32_t* p = st + (((ks * 8 + mt) * 32 + lane) << 2) + reg;
    p[0] = h01;
    p[4] = h23;   // k0+2,k0+3 -> lane+1, same reg
}
// B elem (n,k): lane=((n&7)<<2)|((k&15)>>1 & 3), reg=(k&8)>>3
__device__ __forceinline__ void sts_fragB(uint32_t* st, int nrow, int k0,
                                          uint32_t h01, uint32_t h23) {
    int ks = k0 >> 4, kin = k0 & 15;
    int lane = ((nrow & 7) << 2) | ((kin >> 1) & 3);
    int reg = kin >> 3;
    int nt = nrow >> 3;
    uint32_t* p = st + OFF_FB + (((ks * 16 + nt) * 32 + lane) << 1) + reg;
    p[0] = h01;
    p[2] = h23;
}

// ---------------- K5: fp16 mma.sync GEMM + fused epilogue ----------------
__global__ __launch_bounds__(256) void k_main(
    const float* __restrict__ A,              // text_enc [16384][1024]
    const float* __restrict__ W,              // weight   [1024][1024]
    const int* __restrict__ prompt_ids,
    const uint8_t* __restrict__ initted,
    const float* __restrict__ outputs_table,  // [512][256][1024]
    float* __restrict__ out) {
    extern __shared__ uint32_t su[];

    const int tid = threadIdx.x;
    const int wid = tid >> 5, lane = tid & 31;
    const int wm = wid & 1, wn = wid >> 1;     // warp tile: rows 64*wm, cols 32*wn
    const int m0 = blockIdx.y * BM;
    const int n0 = blockIdx.x * BN;

    // producer mapping
    const int prow = tid >> 1;                 // 0..127
    const int pk = (tid & 1) * 16;             // 0 or 16
    const float* Aptr = A + (size_t)(m0 + prow) * DIM + pk;
    const float* Bptr = W + (size_t)(n0 + prow) * DIM + pk;

    float acc[4][4][4];
#pragma unroll
    for (int i = 0; i < 4; i++)
#pragma unroll
        for (int j = 0; j < 4; j++)
#pragma unroll
            for (int r = 0; r < 4; r++) acc[i][j][r] = 0.0f;

    float4 pa[4], pb[4];
#pragma unroll
    for (int u = 0; u < 4; u++) {
        pa[u] = *(const float4*)(Aptr + u * 4);
        pb[u] = *(const float4*)(Bptr + u * 4);
    }
#pragma unroll
    for (int u = 0; u < 4; u++) {
        sts_fragA(su, prow, pk + u * 4,
                  h2u(__floats2half2_rn(pa[u].x, pa[u].y)),
                  h2u(__floats2half2_rn(pa[u].z, pa[u].w)));
        sts_fragB(su, prow, pk + u * 4,
                  h2u(__floats2half2_rn(pb[u].x, pb[u].y)),
                  h2u(__floats2half2_rn(pb[u].z, pb[u].w)));
    }
    __syncthreads();

    for (int kt = 0; kt < NKT; kt++) {
        uint32_t* cur = su + (kt & 1) * STAGE_U32;
        if (kt + 1 < NKT) {
            const float* Ap = Aptr + (kt + 1) * BK;
            const float* Bp = Bptr + (kt + 1) * BK;
#pragma unroll
            for (int u = 0; u < 4; u++) {
                pa[u] = *(const float4*)(Ap + u * 4);
                pb[u] = *(const float4*)(Bp + u * 4);
            }
        }
        // 2 k16-steps per chunk
#pragma unroll
        for (int ks = 0; ks < 2; ks++) {
            uint4 afr[4];
            uint2 bfr[4];
#pragma unroll
            for (int i = 0; i < 4; i++)
                afr[i] = *(const uint4*)(cur + (((ks * 8 + wm * 4 + i) * 32 + lane) << 2));
#pragma unroll
            for (int j = 0; j < 4; j++)
                bfr[j] = *(const uint2*)(cur + OFF_FB + (((ks * 16 + wn * 4 + j) * 32 + lane) << 1));
#pragma unroll
            for (int i = 0; i < 4; i++)
#pragma unroll
                for (int j = 0; j < 4; j++)
                    mma_f16(acc[i][j], afr[i], bfr[j]);
        }
        if (kt + 1 < NKT) {
            __syncthreads();
            uint32_t* nxt = su + ((kt + 1) & 1) * STAGE_U32;
#pragma unroll
            for (int u = 0; u < 4; u++) {
                sts_fragA(nxt, prow, pk + u * 4,
                          h2u(__floats2half2_rn(pa[u].x, pa[u].y)),
                          h2u(__floats2half2_rn(pa[u].z, pa[u].w)));
                sts_fragB(nxt, prow, pk + u * 4,
                          h2u(__floats2half2_rn(pb[u].x, pb[u].y)),
                          h2u(__floats2half2_rn(pb[u].z, pb[u].w)));
            }
            __syncthreads();
        }
    }

    // ---------------- fused epilogue (same as R3) ----------------
    const int b = m0 >> 8;
    const int pid = prompt_ids[b];
    const bool init = initted[pid] != 0;

    float2 co2[4];
#pragma unroll
    for (int j = 0; j < 4; j++)
        co2[j] = *(const float2*)&g_co[b * DIM + n0 + wn * 32 + j * 8 + (lane & 3) * 2];

#pragma unroll
    for (int i = 0; i < 4; i++) {
        int gr0 = m0 + wm * 64 + i * 16 + (lane >> 2);
        int gr1 = gr0 + 8;
        float simn0 = g_simn[gr0], sig0 = g_sig[gr0];
        float simn1 = g_simn[gr1], sig1 = g_sig[gr1];
        const float* ot0 = outputs_table + ((size_t)pid * SEQ + (gr0 & (SEQ - 1))) * DIM;
        const float* ot1 = outputs_table + ((size_t)pid * SEQ + (gr1 & (SEQ - 1))) * DIM;
#pragma unroll
        for (int j = 0; j < 4; j++) {
            int col = n0 + wn * 32 + j * 8 + (lane & 3) * 2;
            float c0 = acc[i][j][0], c1 = acc[i][j][1];
            float c2 = acc[i][j][2], c3 = acc[i][j][3];
            float o0 = init ? ot0[col] : c0;
            float o1 = init ? ot0[col + 1] : c1;
            float o2 = init ? ot1[col] : c2;
            float o3 = init ? ot1[col + 1] : c3;
            float2 v0 = make_float2(c0 - simn0 * co2[j].x + sig0 * o0,
                                    c1 - simn0 * co2[j].y + sig0 * o1);
            float2 v1 = make_float2(c2 - simn1 * co2[j].x + sig1 * o2,
                                    c3 - simn1 * co2[j].y + sig1 * o3);
            *(float2*)&out[(size_t)gr0 * DIM + col] = v0;
            *(float2*)&out[(size_t)gr1 * DIM + col] = v1;
        }
    }
}

// --------------------------------- launch ---------------------------------------
extern "C" void kernel_launch(void* const* d_in, const int* in_sizes, int n_in,
                              void* d_out, int out_size) {
    const int*     prompt_ids      = (const int*)d_in[0];
    const float*   text_enc        = (const float*)d_in[1];
    const int*     concept_indices = (const int*)d_in[2];
    const float*   weight          = (const float*)d_in[3];
    const float*   C_inv           = (const float*)d_in[4];
    const uint8_t* initted         = (const uint8_t*)d_in[5];
    const float*   ema_table       = (const float*)d_in[6];
    const float*   outputs_table   = (const float*)d_in[7];
    float*         out             = (float*)d_out;

    (void)in_sizes; (void)n_in; (void)out_size;

    cudaFuncSetAttribute(k_main, cudaFuncAttributeMaxDynamicSharedMemorySize, SMEM_TOTAL);

    k_transpose<<<dim3(DIM / 32, DIM / 32), dim3(32, 8)>>>(weight);
    k_gather<<<BATCH, 256>>>(prompt_ids, concept_indices, initted, ema_table, text_enc);
    k_smallgemm<<<dim3(DIM / 128, BATCH / 8, 2), 128>>>(C_inv);
    k_energy<<<BATCH, 256>>>();
    k_sim<<<(BATCH * SEQ) / 8, 256>>>(text_enc);
    k_main<<<dim3(DIM / BN, (BATCH * SEQ) / BM), 256, SMEM_TOTAL>>>(
        text_enc, weight, prompt_ids, initted, outputs_table, out);
}

// round 7
// speedup vs baseline: 5.6813x; 1.6042x over previous
#include <cuda_runtime.h>
#include <cuda_fp16.h>
#include <stdint.h>
#include <math.h>

#define BATCH 64
#define SEQ   256
#define DIM   1024
#define BETA_C 0.75f
#define TEMP_C 0.1f

// ---- GEMM tiling ----
#define BM 128
#define BN 128
#define BK 32
#define NKT (DIM / BK)              // 32 k-chunks
#define STAGES 4
#define STAGE_BYTES 16384           // A 8KB + B 8KB (halves)
#define SMEM_TOTAL (STAGES * STAGE_BYTES)   // 64 KB

// ---------------- device scratch ----------------
__device__ float g_i[BATCH * DIM];
__device__ float g_iCi[BATCH * DIM];
__device__ float g_co[BATCH * DIM];
__device__ float g_E[BATCH];
__device__ float g_simn[BATCH * SEQ];
__device__ float g_sig[BATCH * SEQ];
__device__ float g_Wt[DIM * DIM];
__device__ __half g_Ah[BATCH * SEQ * DIM];   // text_enc in fp16
__device__ __half g_Wh[DIM * DIM];           // weight in fp16

// ---------------- K0: transpose weight ----------------
__global__ void k_transpose(const float* __restrict__ W) {
    __shared__ float t[32][33];
    int x = blockIdx.x * 32 + threadIdx.x;
    int y0 = blockIdx.y * 32;
#pragma unroll
    for (int j = 0; j < 32; j += 8)
        t[threadIdx.y + j][threadIdx.x] = W[(size_t)(y0 + threadIdx.y + j) * DIM + x];
    __syncthreads();
    int x2 = blockIdx.y * 32 + threadIdx.x;
    int y2 = blockIdx.x * 32;
#pragma unroll
    for (int j = 0; j < 32; j += 8)
        g_Wt[(size_t)(y2 + threadIdx.y + j) * DIM + x2] = t[threadIdx.x][threadIdx.y + j];
}

// ---------------- K0b: fp32 -> fp16 conversions ----------------
__global__ void k_convA(const float* __restrict__ A) {
    size_t i = ((size_t)blockIdx.x * 256 + threadIdx.x) * 8;
    float4 v0 = *(const float4*)(A + i);
    float4 v1 = *(const float4*)(A + i + 4);
    __half2 h[4] = {__floats2half2_rn(v0.x, v0.y), __floats2half2_rn(v0.z, v0.w),
                    __floats2half2_rn(v1.x, v1.y), __floats2half2_rn(v1.z, v1.w)};
    *(uint4*)(g_Ah + i) = *(uint4*)h;
}
__global__ void k_convW(const float* __restrict__ W) {
    size_t i = ((size_t)blockIdx.x * 256 + threadIdx.x) * 8;
    float4 v0 = *(const float4*)(W + i);
    float4 v1 = *(const float4*)(W + i + 4);
    __half2 h[4] = {__floats2half2_rn(v0.x, v0.y), __floats2half2_rn(v0.z, v0.w),
                    __floats2half2_rn(v1.x, v1.y), __floats2half2_rn(v1.z, v1.w)};
    *(uint4*)(g_Wh + i) = *(uint4*)h;
}

// ---------------- K1: gather i ----------------
__global__ void k_gather(const int* __restrict__ prompt_ids,
                         const int* __restrict__ concept_indices,
                         const uint8_t* __restrict__ initted,
                         const float* __restrict__ ema_table,
                         const float* __restrict__ text_enc) {
    int b = blockIdx.x;
    int pid = prompt_ids[b];
    int ci = concept_indices[b];
    bool init = initted[pid] != 0;
    const float* src = init ? (ema_table + (size_t)pid * DIM)
                            : (text_enc + ((size_t)b * SEQ + ci) * DIM);
    for (int d = threadIdx.x; d < DIM; d += blockDim.x)
        g_i[b * DIM + d] = src[d];
}

// ---------------- K2: small GEMMs ----------------
__global__ void k_smallgemm(const float* __restrict__ Cinv) {
    const float* __restrict__ M = (blockIdx.z == 0) ? Cinv : g_Wt;
    float* __restrict__ out = (blockIdx.z == 0) ? g_iCi : g_co;
    int d = blockIdx.x * 128 + threadIdx.x;
    int b0 = blockIdx.y * 8;
    __shared__ float ish[8][128];
    float acc[8];
#pragma unroll
    for (int r = 0; r < 8; r++) acc[r] = 0.0f;
    for (int k0 = 0; k0 < DIM; k0 += 128) {
#pragma unroll
        for (int r = 0; r < 8; r++)
            ish[r][threadIdx.x] = g_i[(b0 + r) * DIM + k0 + threadIdx.x];
        __syncthreads();
#pragma unroll 4
        for (int kk = 0; kk < 128; kk++) {
            float m = M[(size_t)(k0 + kk) * DIM + d];
#pragma unroll
            for (int r = 0; r < 8; r++) acc[r] += ish[r][kk] * m;
        }
        __syncthreads();
    }
#pragma unroll
    for (int r = 0; r < 8; r++) out[(b0 + r) * DIM + d] = acc[r];
}

// ---------------- K3: i_energy ----------------
__global__ void k_energy() {
    int b = blockIdx.x, tid = threadIdx.x;
    float s = 0.0f;
    for (int d = tid; d < DIM; d += 256)
        s += g_iCi[b * DIM + d] * g_i[b * DIM + d];
#pragma unroll
    for (int o = 16; o; o >>= 1) s += __shfl_xor_sync(0xffffffffu, s, o);
    __shared__ float red[8];
    if ((tid & 31) == 0) red[tid >> 5] = s;
    __syncthreads();
    if (tid < 8) {
        float t = red[tid];
#pragma unroll
        for (int o = 4; o; o >>= 1) t += __shfl_xor_sync(0xffu, t, o);
        if (tid == 0) g_E[b] = t;
    }
}

// ---------------- K4: sim + sigmoid ----------------
__global__ void k_sim(const float* __restrict__ text_enc) {
    int warp = threadIdx.x >> 5, lane = threadIdx.x & 31;
    int m = blockIdx.x * 8 + warp;
    int b = m >> 8;
    const float4* x = (const float4*)(text_enc + (size_t)m * DIM);
    const float4* c = (const float4*)(g_iCi + (size_t)b * DIM);
    float s = 0.0f;
#pragma unroll
    for (int it = 0; it < 8; it++) {
        int idx = it * 32 + lane;
        float4 xv = x[idx], cv = c[idx];
        s += xv.x * cv.x + xv.y * cv.y + xv.z * cv.z + xv.w * cv.w;
    }
#pragma unroll
    for (int o = 16; o; o >>= 1) s += __shfl_xor_sync(0xffffffffu, s, o);
    if (lane == 0) {
        float simn = s / g_E[b];
        g_simn[m] = simn;
        g_sig[m] = 1.0f / (1.0f + expf(-(simn - BETA_C) / TEMP_C));
    }
}

// ---------------- PTX helpers ----------------
__device__ __forceinline__ uint32_t smem_u32(const void* p) {
    uint32_t a;
    asm("{ .reg .u64 t; cvta.to.shared.u64 t, %1; cvt.u32.u64 %0, t; }" : "=r"(a) : "l"(p));
    return a;
}
__device__ __forceinline__ void cp16(uint32_t dst, const void* src) {
    asm volatile("cp.async.cg.shared.global [%0], [%1], 16;" :: "r"(dst), "l"(src) : "memory");
}
#define CP_COMMIT() asm volatile("cp.async.commit_group;" ::: "memory")
#define CP_WAIT2()  asm volatile("cp.async.wait_group 2;" ::: "memory")
__device__ __forceinline__ uint4 ldsm4(uint32_t addr) {
    uint4 v;
    asm volatile("ldmatrix.sync.aligned.m8n8.x4.shared.b16 {%0,%1,%2,%3}, [%4];"
                 : "=r"(v.x), "=r"(v.y), "=r"(v.z), "=r"(v.w) : "r"(addr));
    return v;
}
__device__ __forceinline__ void mma_f16(float* c, const uint4& a, uint32_t b0, uint32_t b1) {
    asm volatile(
        "mma.sync.aligned.m16n8k16.row.col.f32.f16.f16.f32 "
        "{%0,%1,%2,%3}, {%4,%5,%6,%7}, {%8,%9}, {%0,%1,%2,%3};"
        : "+f"(c[0]), "+f"(c[1]), "+f"(c[2]), "+f"(c[3])
        : "r"(a.x), "r"(a.y), "r"(a.z), "r"(a.w), "r"(b0), "r"(b1));
}
// physical byte offset of (row, 16B-chunk c) in an 8KB half-tile [128 rows x 64B], swizzled
__device__ __forceinline__ uint32_t phys(int r, int c) {
    uint32_t line = r >> 1;
    uint32_t u = ((r & 1) << 2) | c;
    return line * 128 + ((u ^ (line & 7)) << 4);
}

// ---------------- K5: fp16 cp.async + ldmatrix GEMM + fused epilogue ----------------
__global__ __launch_bounds__(256) void k_main(
    const int* __restrict__ prompt_ids,
    const uint8_t* __restrict__ initted,
    const float* __restrict__ outputs_table,  // [512][256][1024]
    float* __restrict__ out) {
    extern __shared__ char smem[];
    const uint32_t sb = smem_u32(smem);

    const int tid = threadIdx.x;
    const int wid = tid >> 5, lane = tid & 31;
    const int wm = wid & 1, wn = wid >> 1;     // warp tile rows 64*wm, cols 32*wn
    const int m0 = blockIdx.y * BM;
    const int n0 = blockIdx.x * BN;

    // ---- producer mapping: 2 A chunks + 2 B chunks per thread per stage ----
    const int chA0 = tid, chA1 = tid + 256;    // 0..511
    const int rA0 = chA0 >> 2, cA0 = chA0 & 3;
    const int rA1 = chA1 >> 2, cA1 = chA1 & 3;
    const __half* srcA0 = g_Ah + (size_t)(m0 + rA0) * DIM + cA0 * 8;
    const __half* srcA1 = g_Ah + (size_t)(m0 + rA1) * DIM + cA1 * 8;
    const __half* srcB0 = g_Wh + (size_t)(n0 + rA0) * DIM + cA0 * 8;
    const __half* srcB1 = g_Wh + (size_t)(n0 + rA1) * DIM + cA1 * 8;
    const uint32_t dA0 = phys(rA0, cA0), dA1 = phys(rA1, cA1);
    const uint32_t dB0 = 8192 + dA0, dB1 = 8192 + dA1;

    // ---- consumer ldmatrix offsets (per lane, constant over kt) ----
    const int lane15 = lane & 15, lanehi = lane >> 4;
    uint32_t offA[4][2], offB[2][2];
#pragma unroll
    for (int i = 0; i < 4; i++)
#pragma unroll
        for (int ks = 0; ks < 2; ks++)
            offA[i][ks] = phys(wm * 64 + i * 16 + lane15, ks * 2 + lanehi);
#pragma unroll
    for (int j2 = 0; j2 < 2; j2++)
#pragma unroll
        for (int ks = 0; ks < 2; ks++)
            offB[j2][ks] = 8192 + phys(wn * 32 + j2 * 16 + lane15, ks * 2 + lanehi);

    float acc[4][4][4];
#pragma unroll
    for (int i = 0; i < 4; i++)
#pragma unroll
        for (int j = 0; j < 4; j++)
#pragma unroll
            for (int r = 0; r < 4; r++) acc[i][j][r] = 0.0f;

    // ---- prologue: issue stages 0..2 ----
#pragma unroll
    for (int s = 0; s < 3; s++) {
        uint32_t base = sb + s * STAGE_BYTES;
        int ko = s * BK;
        cp16(base + dA0, srcA0 + ko);
        cp16(base + dA1, srcA1 + ko);
        cp16(base + dB0, srcB0 + ko);
        cp16(base + dB1, srcB1 + ko);
        CP_COMMIT();
    }

    for (int kt = 0; kt < NKT; kt++) {
        CP_WAIT2();
        __syncthreads();
        uint32_t base = sb + (kt & (STAGES - 1)) * STAGE_BYTES;
#pragma unroll
        for (int ks = 0; ks < 2; ks++) {
            uint4 af[4], bf[2];
#pragma unroll
            for (int i = 0; i < 4; i++) af[i] = ldsm4(base + offA[i][ks]);
#pragma unroll
            for (int j2 = 0; j2 < 2; j2++) bf[j2] = ldsm4(base + offB[j2][ks]);
#pragma unroll
            for (int i = 0; i < 4; i++) {
                mma_f16(acc[i][0], af[i], bf[0].x, bf[0].z);
                mma_f16(acc[i][1], af[i], bf[0].y, bf[0].w);
                mma_f16(acc[i][2], af[i], bf[1].x, bf[1].z);
                mma_f16(acc[i][3], af[i], bf[1].y, bf[1].w);
            }
        }
        if (kt + 3 < NKT) {
            uint32_t nb = sb + ((kt + 3) & (STAGES - 1)) * STAGE_BYTES;
            int ko = (kt + 3) * BK;
            cp16(nb + dA0, srcA0 + ko);
            cp16(nb + dA1, srcA1 + ko);
            cp16(nb + dB0, srcB0 + ko);
            cp16(nb + dB1, srcB1 + ko);
        }
        CP_COMMIT();
    }

    // ---------------- fused epilogue ----------------
    const int b = m0 >> 8;
    const int pid = prompt_ids[b];
    const bool init = initted[pid] != 0;

    float2 co2[4];
#pragma unroll
    for (int j = 0; j < 4; j++)
        co2[j] = *(const float2*)&g_co[b * DIM + n0 + wn * 32 + j * 8 + (lane & 3) * 2];

#pragma unroll
    for (int i = 0; i < 4; i++) {
        int gr0 = m0 + wm * 64 + i * 16 + (lane >> 2);
        int gr1 = gr0 + 8;
        float simn0 = g_simn[gr0], sig0 = g_sig[gr0];
        float simn1 = g_simn[gr1], sig1 = g_sig[gr1];
        const float* ot0 = outputs_table + ((size_t)pid * SEQ + (gr0 & (SEQ - 1))) * DIM;
        const float* ot1 = outputs_table + ((size_t)pid * SEQ + (gr1 & (SEQ - 1))) * DIM;
#pragma unroll
        for (int j = 0; j < 4; j++) {
            int col = n0 + wn * 32 + j * 8 + (lane & 3) * 2;
            float c0 = acc[i][j][0], c1 = acc[i][j][1];
            float c2 = acc[i][j][2], c3 = acc[i][j][3];
            float o0 = init ? ot0[col] : c0;
            float o1 = init ? ot0[col + 1] : c1;
            float o2 = init ? ot1[col] : c2;
            float o3 = init ? ot1[col + 1] : c3;
            float2 v0 = make_float2(c0 - simn0 * co2[j].x + sig0 * o0,
                                    c1 - simn0 * co2[j].y + sig0 * o1);
            float2 v1 = make_float2(c2 - simn1 * co2[j].x + sig1 * o2,
                                    c3 - simn1 * co2[j].y + sig1 * o3);
            *(float2*)&out[(size_t)gr0 * DIM + col] = v0;
            *(float2*)&out[(size_t)gr1 * DIM + col] = v1;
        }
    }
}

// --------------------------------- launch ---------------------------------------
extern "C" void kernel_launch(void* const* d_in, const int* in_sizes, int n_in,
                              void* d_out, int out_size) {
    const int*     prompt_ids      = (const int*)d_in[0];
    const float*   text_enc        = (const float*)d_in[1];
    const int*     concept_indices = (const int*)d_in[2];
    const float*   weight          = (const float*)d_in[3];
    const float*   C_inv           = (const float*)d_in[4];
    const uint8_t* initted         = (const uint8_t*)d_in[5];
    const float*   ema_table       = (const float*)d_in[6];
    const float*   outputs_table   = (const float*)d_in[7];
    float*         out             = (float*)d_out;

    (void)in_sizes; (void)n_in; (void)out_size;

    cudaFuncSetAttribute(k_main, cudaFuncAttributeMaxDynamicSharedMemorySize, SMEM_TOTAL);

    k_convA<<<(BATCH * SEQ * DIM) / (8 * 256), 256>>>(text_enc);
    k_convW<<<(DIM * DIM) / (8 * 256), 256>>>(weight);
    k_transpose<<<dim3(DIM / 32, DIM / 32), dim3(32, 8)>>>(weight);
    k_gather<<<BATCH, 256>>>(prompt_ids, concept_indices, initted, ema_table, text_enc);
    k_smallgemm<<<dim3(DIM / 128, BATCH / 8, 2), 128>>>(C_inv);
    k_energy<<<BATCH, 256>>>();
    k_sim<<<(BATCH * SEQ) / 8, 256>>>(text_enc);
    k_main<<<dim3(DIM / BN, (BATCH * SEQ) / BM), 256, SMEM_TOTAL>>>(
        prompt_ids, initted, outputs_table, out);
}

// round 8
// speedup vs baseline: 5.7235x; 1.0074x over previous
#include <cuda_runtime.h>
#include <cuda_fp16.h>
#include <stdint.h>
#include <math.h>

#define BATCH 64
#define SEQ   256
#define DIM   1024
#define BETA_C 0.75f
#define TEMP_C 0.1f

// ---- GEMM tiling ----
#define BM 128
#define BN 128
#define BK 32
#define NKT (DIM / BK)              // 32 k-chunks
#define STAGES 4
#define STAGE_BYTES 16384           // A 8KB + B 8KB (halves)
#define SMEM_TOTAL (STAGES * STAGE_BYTES)   // 64 KB

// ---------------- device scratch ----------------
__device__ float g_i[BATCH * DIM];
__device__ float g_iCi[BATCH * DIM];
__device__ float g_co[BATCH * DIM];
__device__ float g_E[BATCH];
__device__ float g_simn[BATCH * SEQ];
__device__ float g_sig[BATCH * SEQ];
__device__ float g_Wt[DIM * DIM];
__device__ __half g_Ah[BATCH * SEQ * DIM];   // text_enc in fp16
__device__ __half g_Wh[DIM * DIM];           // weight in fp16

// ---------------- K0: transpose weight + fp16 convert (single read of W) -------
__global__ void k_prepW(const float* __restrict__ W) {
    __shared__ float t[32][33];
    int x = blockIdx.x * 32 + threadIdx.x;
    int y0 = blockIdx.y * 32;
#pragma unroll
    for (int j = 0; j < 32; j += 8) {
        float v = W[(size_t)(y0 + threadIdx.y + j) * DIM + x];
        t[threadIdx.y + j][threadIdx.x] = v;
        g_Wh[(size_t)(y0 + threadIdx.y + j) * DIM + x] = __float2half_rn(v);
    }
    __syncthreads();
    int x2 = blockIdx.y * 32 + threadIdx.x;
    int y2 = blockIdx.x * 32;
#pragma unroll
    for (int j = 0; j < 32; j += 8)
        g_Wt[(size_t)(y2 + threadIdx.y + j) * DIM + x2] = t[threadIdx.x][threadIdx.y + j];
}

// ---------------- K0b: fp32 -> fp16 conversion of A ----------------
__global__ void k_convA(const float* __restrict__ A) {
    size_t i = ((size_t)blockIdx.x * 256 + threadIdx.x) * 8;
    float4 v0 = *(const float4*)(A + i);
    float4 v1 = *(const float4*)(A + i + 4);
    __half2 h[4] = {__floats2half2_rn(v0.x, v0.y), __floats2half2_rn(v0.z, v0.w),
                    __floats2half2_rn(v1.x, v1.y), __floats2half2_rn(v1.z, v1.w)};
    *(uint4*)(g_Ah + i) = *(uint4*)h;
}

// ---------------- K1: gather i ----------------
__global__ void k_gather(const int* __restrict__ prompt_ids,
                         const int* __restrict__ concept_indices,
                         const uint8_t* __restrict__ initted,
                         const float* __restrict__ ema_table,
                         const float* __restrict__ text_enc) {
    int b = blockIdx.x;
    int pid = prompt_ids[b];
    int ci = concept_indices[b];
    bool init = initted[pid] != 0;
    const float* src = init ? (ema_table + (size_t)pid * DIM)
                            : (text_enc + ((size_t)b * SEQ + ci) * DIM);
    for (int d = threadIdx.x; d < DIM; d += blockDim.x)
        g_i[b * DIM + d] = src[d];
}

// ---------------- K2: small GEMMs ----------------
__global__ void k_smallgemm(const float* __restrict__ Cinv) {
    const float* __restrict__ M = (blockIdx.z == 0) ? Cinv : g_Wt;
    float* __restrict__ out = (blockIdx.z == 0) ? g_iCi : g_co;
    int d = blockIdx.x * 128 + threadIdx.x;
    int b0 = blockIdx.y * 8;
    __shared__ float ish[8][128];
    float acc[8];
#pragma unroll
    for (int r = 0; r < 8; r++) acc[r] = 0.0f;
    for (int k0 = 0; k0 < DIM; k0 += 128) {
#pragma unroll
        for (int r = 0; r < 8; r++)
            ish[r][threadIdx.x] = g_i[(b0 + r) * DIM + k0 + threadIdx.x];
        __syncthreads();
#pragma unroll 4
        for (int kk = 0; kk < 128; kk++) {
            float m = M[(size_t)(k0 + kk) * DIM + d];
#pragma unroll
            for (int r = 0; r < 8; r++) acc[r] += ish[r][kk] * m;
        }
        __syncthreads();
    }
#pragma unroll
    for (int r = 0; r < 8; r++) out[(b0 + r) * DIM + d] = acc[r];
}

// ---------------- K3: i_energy ----------------
__global__ void k_energy() {
    int b = blockIdx.x, tid = threadIdx.x;
    float s = 0.0f;
    for (int d = tid; d < DIM; d += 256)
        s += g_iCi[b * DIM + d] * g_i[b * DIM + d];
#pragma unroll
    for (int o = 16; o; o >>= 1) s += __shfl_xor_sync(0xffffffffu, s, o);
    __shared__ float red[8];
    if ((tid & 31) == 0) red[tid >> 5] = s;
    __syncthreads();
    if (tid < 8) {
        float t = red[tid];
#pragma unroll
        for (int o = 4; o; o >>= 1) t += __shfl_xor_sync(0xffu, t, o);
        if (tid == 0) g_E[b] = t;
    }
}

// ---------------- K4: sim + sigmoid ----------------
__global__ void k_sim(const float* __restrict__ text_enc) {
    int warp = threadIdx.x >> 5, lane = threadIdx.x & 31;
    int m = blockIdx.x * 8 + warp;
    int b = m >> 8;
    const float4* x = (const float4*)(text_enc + (size_t)m * DIM);
    const float4* c = (const float4*)(g_iCi + (size_t)b * DIM);
    float s = 0.0f;
#pragma unroll
    for (int it = 0; it < 8; it++) {
        int idx = it * 32 + lane;
        float4 xv = x[idx], cv = c[idx];
        s += xv.x * cv.x + xv.y * cv.y + xv.z * cv.z + xv.w * cv.w;
    }
#pragma unroll
    for (int o = 16; o; o >>= 1) s += __shfl_xor_sync(0xffffffffu, s, o);
    if (lane == 0) {
        float simn = s / g_E[b];
        g_simn[m] = simn;
        g_sig[m] = 1.0f / (1.0f + expf(-(simn - BETA_C) / TEMP_C));
    }
}

// ---------------- PTX helpers ----------------
__device__ __forceinline__ uint32_t smem_u32(const void* p) {
    uint32_t a;
    asm("{ .reg .u64 t; cvta.to.shared.u64 t, %1; cvt.u32.u64 %0, t; }" : "=r"(a) : "l"(p));
    return a;
}
__device__ __forceinline__ void cp16(uint32_t dst, const void* src) {
    asm volatile("cp.async.cg.shared.global [%0], [%1], 16;" :: "r"(dst), "l"(src) : "memory");
}
#define CP_COMMIT() asm volatile("cp.async.commit_group;" ::: "memory")
#define CP_WAIT2()  asm volatile("cp.async.wait_group 2;" ::: "memory")
__device__ __forceinline__ uint4 ldsm4(uint32_t addr) {
    uint4 v;
    asm volatile("ldmatrix.sync.aligned.m8n8.x4.shared.b16 {%0,%1,%2,%3}, [%4];"
                 : "=r"(v.x), "=r"(v.y), "=r"(v.z), "=r"(v.w) : "r"(addr));
    return v;
}
__device__ __forceinline__ void mma_f16(float* c, const uint4& a, uint32_t b0, uint32_t b1) {
    asm volatile(
        "mma.sync.aligned.m16n8k16.row.col.f32.f16.f16.f32 "
        "{%0,%1,%2,%3}, {%4,%5,%6,%7}, {%8,%9}, {%0,%1,%2,%3};"
        : "+f"(c[0]), "+f"(c[1]), "+f"(c[2]), "+f"(c[3])
        : "r"(a.x), "r"(a.y), "r"(a.z), "r"(a.w), "r"(b0), "r"(b1));
}
// physical byte offset of (row, 16B-chunk c) in an 8KB half-tile [128 rows x 64B], swizzled
__device__ __forceinline__ uint32_t phys(int r, int c) {
    uint32_t line = r >> 1;
    uint32_t u = ((r & 1) << 2) | c;
    return line * 128 + ((u ^ (line & 7)) << 4);
}

// ---------------- K5: fp16 cp.async + ldmatrix GEMM + fused epilogue ----------------
__global__ __launch_bounds__(256, 2) void k_main(
    const int* __restrict__ prompt_ids,
    const uint8_t* __restrict__ initted,
    const float* __restrict__ outputs_table,  // [512][256][1024]
    float* __restrict__ out) {
    extern __shared__ char smem[];
    const uint32_t sb = smem_u32(smem);

    const int tid = threadIdx.x;
    const int wid = tid >> 5, lane = tid & 31;
    const int wm = wid & 1, wn = wid >> 1;     // warp tile rows 64*wm, cols 32*wn
    const int m0 = blockIdx.y * BM;
    const int n0 = blockIdx.x * BN;

    // ---- producer mapping: 2 A chunks + 2 B chunks per thread per stage ----
    const int chA0 = tid, chA1 = tid + 256;    // 0..511
    const int rA0 = chA0 >> 2, cA0 = chA0 & 3;
    const int rA1 = chA1 >> 2, cA1 = chA1 & 3;
    const __half* srcA0 = g_Ah + (size_t)(m0 + rA0) * DIM + cA0 * 8;
    const __half* srcA1 = g_Ah + (size_t)(m0 + rA1) * DIM + cA1 * 8;
    const __half* srcB0 = g_Wh + (size_t)(n0 + rA0) * DIM + cA0 * 8;
    const __half* srcB1 = g_Wh + (size_t)(n0 + rA1) * DIM + cA1 * 8;
    const uint32_t dA0 = phys(rA0, cA0), dA1 = phys(rA1, cA1);
    const uint32_t dB0 = 8192 + dA0, dB1 = 8192 + dA1;

    // ---- consumer ldmatrix offsets (per lane, constant over kt) ----
    const int lane15 = lane & 15, lanehi = lane >> 4;
    uint32_t offA[4][2], offB[2][2];
#pragma unroll
    for (int i = 0; i < 4; i++)
#pragma unroll
        for (int ks = 0; ks < 2; ks++)
            offA[i][ks] = phys(wm * 64 + i * 16 + lane15, ks * 2 + lanehi);
#pragma unroll
    for (int j2 = 0; j2 < 2; j2++)
#pragma unroll
        for (int ks = 0; ks < 2; ks++)
            offB[j2][ks] = 8192 + phys(wn * 32 + j2 * 16 + lane15, ks * 2 + lanehi);

    float acc[4][4][4];
#pragma unroll
    for (int i = 0; i < 4; i++)
#pragma unroll
        for (int j = 0; j < 4; j++)
#pragma unroll
            for (int r = 0; r < 4; r++) acc[i][j][r] = 0.0f;

    // ---- prologue: issue stages 0..2 ----
#pragma unroll
    for (int s = 0; s < 3; s++) {
        uint32_t base = sb + s * STAGE_BYTES;
        int ko = s * BK;
        cp16(base + dA0, srcA0 + ko);
        cp16(base + dA1, srcA1 + ko);
        cp16(base + dB0, srcB0 + ko);
        cp16(base + dB1, srcB1 + ko);
        CP_COMMIT();
    }

    for (int kt = 0; kt < NKT; kt++) {
        CP_WAIT2();
        __syncthreads();
        uint32_t base = sb + (kt & (STAGES - 1)) * STAGE_BYTES;
#pragma unroll
        for (int ks = 0; ks < 2; ks++) {
            uint4 af[4], bf[2];
#pragma unroll
            for (int i = 0; i < 4; i++) af[i] = ldsm4(base + offA[i][ks]);
#pragma unroll
            for (int j2 = 0; j2 < 2; j2++) bf[j2] = ldsm4(base + offB[j2][ks]);
#pragma unroll
            for (int i = 0; i < 4; i++) {
                mma_f16(acc[i][0], af[i], bf[0].x, bf[0].z);
                mma_f16(acc[i][1], af[i], bf[0].y, bf[0].w);
                mma_f16(acc[i][2], af[i], bf[1].x, bf[1].z);
                mma_f16(acc[i][3], af[i], bf[1].y, bf[1].w);
            }
        }
        if (kt + 3 < NKT) {
            uint32_t nb = sb + ((kt + 3) & (STAGES - 1)) * STAGE_BYTES;
            int ko = (kt + 3) * BK;
            cp16(nb + dA0, srcA0 + ko);
            cp16(nb + dA1, srcA1 + ko);
            cp16(nb + dB0, srcB0 + ko);
            cp16(nb + dB1, srcB1 + ko);
        }
        CP_COMMIT();
    }

    // ---------------- fused epilogue ----------------
    const int b = m0 >> 8;
    const int pid = prompt_ids[b];
    const bool init = initted[pid] != 0;

    float2 co2[4];
#pragma unroll
    for (int j = 0; j < 4; j++)
        co2[j] = *(const float2*)&g_co[b * DIM + n0 + wn * 32 + j * 8 + (lane & 3) * 2];

#pragma unroll
    for (int i = 0; i < 4; i++) {
        int gr0 = m0 + wm * 64 + i * 16 + (lane >> 2);
        int gr1 = gr0 + 8;
        float simn0 = g_simn[gr0], sig0 = g_sig[gr0];
        float simn1 = g_simn[gr1], sig1 = g_sig[gr1];
        const float* ot0 = outputs_table + ((size_t)pid * SEQ + (gr0 & (SEQ - 1))) * DIM;
        const float* ot1 = outputs_table + ((size_t)pid * SEQ + (gr1 & (SEQ - 1))) * DIM;
#pragma unroll
        for (int j = 0; j < 4; j++) {
            int col = n0 + wn * 32 + j * 8 + (lane & 3) * 2;
            float c0 = acc[i][j][0], c1 = acc[i][j][1];
            float c2 = acc[i][j][2], c3 = acc[i][j][3];
            float o0 = init ? ot0[col] : c0;
            float o1 = init ? ot0[col + 1] : c1;
            float o2 = init ? ot1[col] : c2;
            float o3 = init ? ot1[col + 1] : c3;
            float2 v0 = make_float2(c0 - simn0 * co2[j].x + sig0 * o0,
                                    c1 - simn0 * co2[j].y + sig0 * o1);
            float2 v1 = make_float2(c2 - simn1 * co2[j].x + sig1 * o2,
                                    c3 - simn1 * co2[j].y + sig1 * o3);
            *(float2*)&out[(size_t)gr0 * DIM + col] = v0;
            *(float2*)&out[(size_t)gr1 * DIM + col] = v1;
        }
    }
}

// --------------------------------- launch ---------------------------------------
extern "C" void kernel_launch(void* const* d_in, const int* in_sizes, int n_in,
                              void* d_out, int out_size) {
    const int*     prompt_ids      = (const int*)d_in[0];
    const float*   text_enc        = (const float*)d_in[1];
    const int*     concept_indices = (const int*)d_in[2];
    const float*   weight          = (const float*)d_in[3];
    const float*   C_inv           = (const float*)d_in[4];
    const uint8_t* initted         = (const uint8_t*)d_in[5];
    const float*   ema_table       = (const float*)d_in[6];
    const float*   outputs_table   = (const float*)d_in[7];
    float*         out             = (float*)d_out;

    (void)in_sizes; (void)n_in; (void)out_size;

    cudaFuncSetAttribute(k_main, cudaFuncAttributeMaxDynamicSharedMemorySize, SMEM_TOTAL);

    k_convA<<<(BATCH * SEQ * DIM) / (8 * 256), 256>>>(text_enc);
    k_prepW<<<dim3(DIM / 32, DIM / 32), dim3(32, 8)>>>(weight);
    k_gather<<<BATCH, 256>>>(prompt_ids, concept_indices, initted, ema_table, text_enc);
    k_smallgemm<<<dim3(DIM / 128, BATCH / 8, 2), 128>>>(C_inv);
    k_energy<<<BATCH, 256>>>();
    k_sim<<<(BATCH * SEQ) / 8, 256>>>(text_enc);
    k_main<<<dim3(DIM / BN, (BATCH * SEQ) / BM), 256, SMEM_TOTAL>>>(
        prompt_ids, initted, outputs_table, out);
}

// round 9
// speedup vs baseline: 10.0147x; 1.7498x over previous
#include <cuda_runtime.h>
#include <cuda_fp16.h>
#include <stdint.h>
#include <math.h>

#define BATCH 64
#define SEQ   256
#define DIM   1024
#define BETA_C 0.75f
#define TEMP_C 0.1f

// ---- GEMM tiling ----
#define BM 128
#define BN 128
#define BK 32
#define NKT (DIM / BK)              // 32 k-chunks
#define STAGES 4
#define STAGE_BYTES 16384           // A 8KB + B 8KB (halves)
#define SMEM_TOTAL (STAGES * STAGE_BYTES)   // 64 KB

// ---------------- device scratch ----------------
__device__ float g_part[2][4][BATCH][DIM];   // split-K partials: [iCi|co][ks][b][d]
__device__ float g_simn[BATCH * SEQ];
__device__ float g_sig[BATCH * SEQ];
__device__ float g_Wt[DIM * DIM];
__device__ __half g_Ah[BATCH * SEQ * DIM];   // text_enc in fp16
__device__ __half g_Wh[DIM * DIM];           // weight in fp16

// ---------------- K0: transpose weight + fp16 convert (single read of W) -------
__global__ void k_prepW(const float* __restrict__ W) {
    __shared__ float t[32][33];
    int x = blockIdx.x * 32 + threadIdx.x;
    int y0 = blockIdx.y * 32;
#pragma unroll
    for (int j = 0; j < 32; j += 8) {
        float v = W[(size_t)(y0 + threadIdx.y + j) * DIM + x];
        t[threadIdx.y + j][threadIdx.x] = v;
        g_Wh[(size_t)(y0 + threadIdx.y + j) * DIM + x] = __float2half_rn(v);
    }
    __syncthreads();
    int x2 = blockIdx.y * 32 + threadIdx.x;
    int y2 = blockIdx.x * 32;
#pragma unroll
    for (int j = 0; j < 32; j += 8)
        g_Wt[(size_t)(y2 + threadIdx.y + j) * DIM + x2] = t[threadIdx.x][threadIdx.y + j];
}

// ---------------- K1: split-K small GEMMs (inline gather, partial outputs) -----
// out_part[z][ks][b][d] = sum_{k in ks*256..+256} i[b,k] * M_z[k,d]
__global__ __launch_bounds__(128) void k_smallgemm(
    const float* __restrict__ Cinv,
    const int* __restrict__ prompt_ids,
    const int* __restrict__ concept_indices,
    const uint8_t* __restrict__ initted,
    const float* __restrict__ ema_table,
    const float* __restrict__ text_enc) {
    const int tx = threadIdx.x;
    const int d = blockIdx.x * 128 + tx;
    const int b0 = blockIdx.y * 8;
    const int z = blockIdx.z >> 2;            // 0: Cinv->iCi, 1: Wt->co
    const int ks = blockIdx.z & 3;
    const float* __restrict__ M = (z == 0) ? Cinv : g_Wt;

    __shared__ const float* srcp[8];
    __shared__ float ish[8][128];
    if (tx < 8) {
        int b = b0 + tx;
        int pid = prompt_ids[b];
        int ci = concept_indices[b];
        bool init = initted[pid] != 0;
        srcp[tx] = init ? (ema_table + (size_t)pid * DIM)
                        : (text_enc + ((size_t)b * SEQ + ci) * DIM);
    }
    __syncthreads();

    float acc[8];
#pragma unroll
    for (int r = 0; r < 8; r++) acc[r] = 0.0f;

    const int kbase = ks * 256;
#pragma unroll
    for (int kh = 0; kh < 2; kh++) {
        int k0 = kbase + kh * 128;
#pragma unroll
        for (int r = 0; r < 8; r++) ish[r][tx] = srcp[r][k0 + tx];
        __syncthreads();
#pragma unroll 4
        for (int kk = 0; kk < 128; kk++) {
            float m = M[(size_t)(k0 + kk) * DIM + d];
#pragma unroll
            for (int r = 0; r < 8; r++) acc[r] += ish[r][kk] * m;
        }
        __syncthreads();
    }
#pragma unroll
    for (int r = 0; r < 8; r++) g_part[z][ks][b0 + r][d] = acc[r];
}

// ---------------- K2: fused iCi-reduce + energy + sim/sigmoid + A fp16 convert --
__global__ __launch_bounds__(256) void k_simE(
    const int* __restrict__ prompt_ids,
    const int* __restrict__ concept_indices,
    const uint8_t* __restrict__ initted,
    const float* __restrict__ ema_table,
    const float* __restrict__ text_enc) {
    __shared__ float sm_iCi[DIM];
    __shared__ float red[8];
    __shared__ float sE;

    const int tid = threadIdx.x;
    const int m0 = blockIdx.x * 8;
    const int b = m0 >> 5 >> 3;               // m0 / 256

    int pid = prompt_ids[b];
    int ci = concept_indices[b];
    bool init = initted[pid] != 0;
    const float* isrc = init ? (ema_table + (size_t)pid * DIM)
                             : (text_enc + ((size_t)b * SEQ + ci) * DIM);

    // phase 1: reduce iCi partials into smem + energy dot
    float s = 0.0f;
    for (int d = tid; d < DIM; d += 256) {
        float v = g_part[0][0][b][d] + g_part[0][1][b][d] +
                  g_part[0][2][b][d] + g_part[0][3][b][d];
        sm_iCi[d] = v;
        s += v * isrc[d];
    }
#pragma unroll
    for (int o = 16; o; o >>= 1) s += __shfl_xor_sync(0xffffffffu, s, o);
    if ((tid & 31) == 0) red[tid >> 5] = s;
    __syncthreads();
    if (tid == 0) {
        float t = 0.0f;
#pragma unroll
        for (int w = 0; w < 8; w++) t += red[w];
        sE = t;
    }
    __syncthreads();

    // phase 2: one warp per row — sim dot + fp16 convert of text_enc row
    const int wr = tid >> 5, lane = tid & 31;
    const int m = m0 + wr;
    const float4* x = (const float4*)(text_enc + (size_t)m * DIM);
    const float4* c4 = (const float4*)sm_iCi;
    __half* arow = g_Ah + (size_t)m * DIM;
    float dot = 0.0f;
#pragma unroll
    for (int it = 0; it < 8; it++) {
        int idx = it * 32 + lane;
        float4 xv = x[idx];
        float4 cv = c4[idx];
        dot += xv.x * cv.x + xv.y * cv.y + xv.z * cv.z + xv.w * cv.w;
        uint2 h;
        h.x = *(uint32_t*)&(__half2&)*(__half2[1]){__floats2half2_rn(xv.x, xv.y)};
        h.y = *(uint32_t*)&(__half2&)*(__half2[1]){__floats2half2_rn(xv.z, xv.w)};
        *(uint2*)(arow + idx * 4) = h;
    }
#pragma unroll
    for (int o = 16; o; o >>= 1) dot += __shfl_xor_sync(0xffffffffu, dot, o);
    if (lane == 0) {
        float simn = dot / sE;
        g_simn[m] = simn;
        g_sig[m] = 1.0f / (1.0f + expf(-(simn - BETA_C) / TEMP_C));
    }
}

// ---------------- PTX helpers ----------------
__device__ __forceinline__ uint32_t smem_u32(const void* p) {
    uint32_t a;
    asm("{ .reg .u64 t; cvta.to.shared.u64 t, %1; cvt.u32.u64 %0, t; }" : "=r"(a) : "l"(p));
    return a;
}
__device__ __forceinline__ void cp16(uint32_t dst, const void* src) {
    asm volatile("cp.async.cg.shared.global [%0], [%1], 16;" :: "r"(dst), "l"(src) : "memory");
}
#define CP_COMMIT() asm volatile("cp.async.commit_group;" ::: "memory")
#define CP_WAIT2()  asm volatile("cp.async.wait_group 2;" ::: "memory")
__device__ __forceinline__ uint4 ldsm4(uint32_t addr) {
    uint4 v;
    asm volatile("ldmatrix.sync.aligned.m8n8.x4.shared.b16 {%0,%1,%2,%3}, [%4];"
                 : "=r"(v.x), "=r"(v.y), "=r"(v.z), "=r"(v.w) : "r"(addr));
    return v;
}
__device__ __forceinline__ void mma_f16(float* c, const uint4& a, uint32_t b0, uint32_t b1) {
    asm volatile(
        "mma.sync.aligned.m16n8k16.row.col.f32.f16.f16.f32 "
        "{%0,%1,%2,%3}, {%4,%5,%6,%7}, {%8,%9}, {%0,%1,%2,%3};"
        : "+f"(c[0]), "+f"(c[1]), "+f"(c[2]), "+f"(c[3])
        : "r"(a.x), "r"(a.y), "r"(a.z), "r"(a.w), "r"(b0), "r"(b1));
}
// physical byte offset of (row, 16B-chunk c) in an 8KB half-tile [128 rows x 64B], swizzled
__device__ __forceinline__ uint32_t phys(int r, int c) {
    uint32_t line = r >> 1;
    uint32_t u = ((r & 1) << 2) | c;
    return line * 128 + ((u ^ (line & 7)) << 4);
}

// ---------------- K3: fp16 cp.async + ldmatrix GEMM + fused epilogue ----------------
__global__ __launch_bounds__(256, 2) void k_main(
    const int* __restrict__ prompt_ids,
    const uint8_t* __restrict__ initted,
    const float* __restrict__ outputs_table,  // [512][256][1024]
    float* __restrict__ out) {
    extern __shared__ char smem[];
    const uint32_t sb = smem_u32(smem);

    const int tid = threadIdx.x;
    const int wid = tid >> 5, lane = tid & 31;
    const int wm = wid & 1, wn = wid >> 1;     // warp tile rows 64*wm, cols 32*wn
    const int m0 = blockIdx.y * BM;
    const int n0 = blockIdx.x * BN;

    // ---- producer mapping: 2 A chunks + 2 B chunks per thread per stage ----
    const int chA0 = tid, chA1 = tid + 256;    // 0..511
    const int rA0 = chA0 >> 2, cA0 = chA0 & 3;
    const int rA1 = chA1 >> 2, cA1 = chA1 & 3;
    const __half* srcA0 = g_Ah + (size_t)(m0 + rA0) * DIM + cA0 * 8;
    const __half* srcA1 = g_Ah + (size_t)(m0 + rA1) * DIM + cA1 * 8;
    const __half* srcB0 = g_Wh + (size_t)(n0 + rA0) * DIM + cA0 * 8;
    const __half* srcB1 = g_Wh + (size_t)(n0 + rA1) * DIM + cA1 * 8;
    const uint32_t dA0 = phys(rA0, cA0), dA1 = phys(rA1, cA1);
    const uint32_t dB0 = 8192 + dA0, dB1 = 8192 + dA1;

    // ---- consumer ldmatrix offsets ----
    const int lane15 = lane & 15, lanehi = lane >> 4;
    uint32_t offA[4][2], offB[2][2];
#pragma unroll
    for (int i = 0; i < 4; i++)
#pragma unroll
        for (int ks = 0; ks < 2; ks++)
            offA[i][ks] = phys(wm * 64 + i * 16 + lane15, ks * 2 + lanehi);
#pragma unroll
    for (int j2 = 0; j2 < 2; j2++)
#pragma unroll
        for (int ks = 0; ks < 2; ks++)
            offB[j2][ks] = 8192 + phys(wn * 32 + j2 * 16 + lane15, ks * 2 + lanehi);

    float acc[4][4][4];
#pragma unroll
    for (int i = 0; i < 4; i++)
#pragma unroll
        for (int j = 0; j < 4; j++)
#pragma unroll
            for (int r = 0; r < 4; r++) acc[i][j][r] = 0.0f;

    // ---- prologue: issue stages 0..2 ----
#pragma unroll
    for (int s = 0; s < 3; s++) {
        uint32_t base = sb + s * STAGE_BYTES;
        int ko = s * BK;
        cp16(base + dA0, srcA0 + ko);
        cp16(base + dA1, srcA1 + ko);
        cp16(base + dB0, srcB0 + ko);
        cp16(base + dB1, srcB1 + ko);
        CP_COMMIT();
    }

    for (int kt = 0; kt < NKT; kt++) {
        CP_WAIT2();
        __syncthreads();
        uint32_t base = sb + (kt & (STAGES - 1)) * STAGE_BYTES;
#pragma unroll
        for (int ks = 0; ks < 2; ks++) {
            uint4 af[4], bf[2];
#pragma unroll
            for (int i = 0; i < 4; i++) af[i] = ldsm4(base + offA[i][ks]);
#pragma unroll
            for (int j2 = 0; j2 < 2; j2++) bf[j2] = ldsm4(base + offB[j2][ks]);
#pragma unroll
            for (int i = 0; i < 4; i++) {
                mma_f16(acc[i][0], af[i], bf[0].x, bf[0].z);
                mma_f16(acc[i][1], af[i], bf[0].y, bf[0].w);
                mma_f16(acc[i][2], af[i], bf[1].x, bf[1].z);
                mma_f16(acc[i][3], af[i], bf[1].y, bf[1].w);
            }
        }
        if (kt + 3 < NKT) {
            uint32_t nb = sb + ((kt + 3) & (STAGES - 1)) * STAGE_BYTES;
            int ko = (kt + 3) * BK;
            cp16(nb + dA0, srcA0 + ko);
            cp16(nb + dA1, srcA1 + ko);
            cp16(nb + dB0, srcB0 + ko);
            cp16(nb + dB1, srcB1 + ko);
        }
        CP_COMMIT();
    }

    // ---------------- fused epilogue ----------------
    const int b = m0 >> 8;
    const int pid = prompt_ids[b];
    const bool init = initted[pid] != 0;

    float2 co2[4];
#pragma unroll
    for (int j = 0; j < 4; j++) {
        int col = n0 + wn * 32 + j * 8 + (lane & 3) * 2;
        float2 v = *(const float2*)&g_part[1][0][b][col];
        float2 v1 = *(const float2*)&g_part[1][1][b][col];
        float2 v2 = *(const float2*)&g_part[1][2][b][col];
        float2 v3 = *(const float2*)&g_part[1][3][b][col];
        co2[j] = make_float2(v.x + v1.x + v2.x + v3.x, v.y + v1.y + v2.y + v3.y);
    }

#pragma unroll
    for (int i = 0; i < 4; i++) {
        int gr0 = m0 + wm * 64 + i * 16 + (lane >> 2);
        int gr1 = gr0 + 8;
        float simn0 = g_simn[gr0], sig0 = g_sig[gr0];
        float simn1 = g_simn[gr1], sig1 = g_sig[gr1];
        const float* ot0 = outputs_table + ((size_t)pid * SEQ + (gr0 & (SEQ - 1))) * DIM;
        const float* ot1 = outputs_table + ((size_t)pid * SEQ + (gr1 & (SEQ - 1))) * DIM;
#pragma unroll
        for (int j = 0; j < 4; j++) {
            int col = n0 + wn * 32 + j * 8 + (lane & 3) * 2;
            float c0 = acc[i][j][0], c1 = acc[i][j][1];
            float c2 = acc[i][j][2], c3 = acc[i][j][3];
            float o0 = init ? ot0[col] : c0;
            float o1 = init ? ot0[col + 1] : c1;
            float o2 = init ? ot1[col] : c2;
            float o3 = init ? ot1[col + 1] : c3;
            float2 v0 = make_float2(c0 - simn0 * co2[j].x + sig0 * o0,
                                    c1 - simn0 * co2[j].y + sig0 * o1);
            float2 v1 = make_float2(c2 - simn1 * co2[j].x + sig1 * o2,
                                    c3 - simn1 * co2[j].y + sig1 * o3);
            *(float2*)&out[(size_t)gr0 * DIM + col] = v0;
            *(float2*)&out[(size_t)gr1 * DIM + col] = v1;
        }
    }
}

// --------------------------------- launch ---------------------------------------
extern "C" void kernel_launch(void* const* d_in, const int* in_sizes, int n_in,
                              void* d_out, int out_size) {
    const int*     prompt_ids      = (const int*)d_in[0];
    const float*   text_enc        = (const float*)d_in[1];
    const int*     concept_indices = (const int*)d_in[2];
    const float*   weight          = (const float*)d_in[3];
    const float*   C_inv           = (const float*)d_in[4];
    const uint8_t* initted         = (const uint8_t*)d_in[5];
    const float*   ema_table       = (const float*)d_in[6];
    const float*   outputs_table   = (const float*)d_in[7];
    float*         out             = (float*)d_out;

    (void)in_sizes; (void)n_in; (void)out_size;

    cudaFuncSetAttribute(k_main, cudaFuncAttributeMaxDynamicSharedMemorySize, SMEM_TOTAL);

    k_prepW<<<dim3(DIM / 32, DIM / 32), dim3(32, 8)>>>(weight);
    k_smallgemm<<<dim3(8, 8, 8), 128>>>(C_inv, prompt_ids, concept_indices,
                                        initted, ema_table, text_enc);
    k_simE<<<(BATCH * SEQ) / 8, 256>>>(prompt_ids, concept_indices, initted,
                                       ema_table, text_enc);
    k_main<<<dim3(DIM / BN, (BATCH * SEQ) / BM), 256, SMEM_TOTAL>>>(
        prompt_ids, initted, outputs_table, out);
}